// round 1
// baseline (speedup 1.0000x reference)
#include <cuda_runtime.h>
#include <cuda_bf16.h>
#include <math.h>

#define FULLMASK 0xffffffffu
#define NCLS 10
#define MAXM 131072
#define MAXN 2048
#define NSPLIT 4

// ---------------- scratch (static device globals; no allocation) ------------
__device__ float g_zc[MAXM * 128];     // encoded candidates, permuted by class
__device__ float g_cn[MAXM];           // ||zc||^2
__device__ float g_z[MAXN * 128];      // encoded queries
__device__ float g_zn2[MAXN];          // ||z||^2
__device__ int   g_destMap[MAXM];      // src -> sorted dest
__device__ int   g_hist[(MAXM / 32) * NCLS];
__device__ int   g_classStart[NCLS + 1];
__device__ float g_part[NSPLIT * MAXN * NCLS];

// ---------------- counting sort by class (deterministic, stable) ------------
__global__ void hist_k(const int* __restrict__ y, int M, int* __restrict__ hist) {
    int i = blockIdx.x * 32 + threadIdx.x;
    int c = (i < M) ? y[i] : -1;
#pragma unroll
    for (int cls = 0; cls < NCLS; ++cls) {
        unsigned b = __ballot_sync(FULLMASK, c == cls);
        if (threadIdx.x == 0) hist[blockIdx.x * NCLS + cls] = __popc(b);
    }
}

__global__ void scan_k(int* hist, int NB, int* classStart) {
    __shared__ int tot[NCLS];
    int c = threadIdx.x;
    if (c < NCLS) {
        int run = 0;
        for (int b = 0; b < NB; ++b) {
            int t = hist[b * NCLS + c];
            hist[b * NCLS + c] = run;   // becomes within-class prefix per block
            run += t;
        }
        tot[c] = run;
    }
    __syncthreads();
    if (threadIdx.x == 0) {
        int a = 0;
        for (int i = 0; i < NCLS; ++i) { classStart[i] = a; a += tot[i]; }
        classStart[NCLS] = a;
    }
}

__global__ void scatter_k(const int* __restrict__ y, int M,
                          const int* __restrict__ hist,
                          const int* __restrict__ classStart,
                          int* __restrict__ dest) {
    int lane = threadIdx.x;
    int i = blockIdx.x * 32 + lane;
    int c = (i < M) ? y[i] : -1;
    unsigned mymask = 0;
#pragma unroll
    for (int cls = 0; cls < NCLS; ++cls) {
        unsigned b = __ballot_sync(FULLMASK, c == cls);
        if (c == cls) mymask = b;
    }
    if (i < M) {
        int rank = __popc(mymask & ((1u << lane) - 1u));
        dest[i] = classStart[c] + hist[blockIdx.x * NCLS + c] + rank;
    }
}

// ---------------- encoder: out[dest] = X[src] @ W^T + b, plus row norms -----
__global__ __launch_bounds__(256, 2)
void encode_k(const float* __restrict__ X, int n, const int* __restrict__ destMap,
              const float* __restrict__ W, const float* __restrict__ bias,
              float* __restrict__ outZ, float* __restrict__ outN) {
    extern __shared__ float sm[];
    float* ws = sm;                       // [128][132]
    float* xs = sm + 128 * 132;           // [32][132]
    int*   dests = (int*)(sm + 128 * 132 + 32 * 132);

    int tid = threadIdx.x;
    int base = blockIdx.x * 32;

    for (int t = tid; t < 128 * 32; t += 256) {
        int row = t >> 5, q = t & 31;
        float4 v = ((const float4*)W)[row * 32 + q];
        *(float4*)&ws[row * 132 + q * 4] = v;
    }
    for (int t = tid; t < 32 * 32; t += 256) {
        int row = t >> 5, q = t & 31;
        float4 v = make_float4(0.f, 0.f, 0.f, 0.f);
        if (base + row < n) v = ((const float4*)X)[(base + row) * 32 + q];
        *(float4*)&xs[row * 132 + q * 4] = v;
    }
    if (tid < 32)
        dests[tid] = (base + tid < n) ? (destMap ? destMap[base + tid] : base + tid) : -1;
    __syncthreads();

    int cgrp = tid & 31, rgrp = tid >> 5;
    float acc[4][4];
#pragma unroll
    for (int i = 0; i < 4; ++i)
#pragma unroll
        for (int j = 0; j < 4; ++j) acc[i][j] = 0.f;

#pragma unroll 4
    for (int k = 0; k < 128; k += 4) {
        float4 a[4], w4[4];
#pragma unroll
        for (int i = 0; i < 4; ++i) a[i] = *(const float4*)&xs[(rgrp * 4 + i) * 132 + k];
#pragma unroll
        for (int j = 0; j < 4; ++j) w4[j] = *(const float4*)&ws[(cgrp + 32 * j) * 132 + k];
#pragma unroll
        for (int i = 0; i < 4; ++i)
#pragma unroll
            for (int j = 0; j < 4; ++j) {
                acc[i][j] = fmaf(a[i].x, w4[j].x, acc[i][j]);
                acc[i][j] = fmaf(a[i].y, w4[j].y, acc[i][j]);
                acc[i][j] = fmaf(a[i].z, w4[j].z, acc[i][j]);
                acc[i][j] = fmaf(a[i].w, w4[j].w, acc[i][j]);
            }
    }

    float nrm[4] = {0.f, 0.f, 0.f, 0.f};
#pragma unroll
    for (int j = 0; j < 4; ++j) {
        int dim = cgrp + 32 * j;
        float bb = bias[dim];
#pragma unroll
        for (int i = 0; i < 4; ++i) {
            float v = acc[i][j] + bb;
            acc[i][j] = v;
            nrm[i] = fmaf(v, v, nrm[i]);
        }
    }
#pragma unroll
    for (int i = 0; i < 4; ++i) {
        int d = dests[rgrp * 4 + i];
        if (d >= 0) {
#pragma unroll
            for (int j = 0; j < 4; ++j) outZ[d * 128 + cgrp + 32 * j] = acc[i][j];
        }
        float s = nrm[i];
#pragma unroll
        for (int off = 16; off > 0; off >>= 1) s += __shfl_xor_sync(FULLMASK, s, off);
        if (cgrp == 0 && d >= 0) outN[d] = s;
    }
}

// ---------------- fused dist + softmax-numerator per class ------------------
__global__ __launch_bounds__(256, 2)
void nca_main_k(const float* __restrict__ z, const float* __restrict__ zn2,
                const float* __restrict__ zc, const float* __restrict__ cn,
                const int* __restrict__ classStart,
                float* __restrict__ part, int M, int N) {
    extern __shared__ float sm[];
    float* css = sm;                 // [128][132] candidate chunk
    float* zs  = sm + 128 * 132;     // [32][132]  query tile

    int tid = threadIdx.x, cgrp = tid & 31, rgrp = tid >> 5;
    int rowBase = blockIdx.x * 32;
    int sy = blockIdx.y;
    int per = M / NSPLIT;
    int splitLo = sy * per;
    int splitHi = splitLo + per;

    for (int t = tid; t < 32 * 32; t += 256) {
        int row = t >> 5, q = t & 31;
        *(float4*)&zs[row * 132 + q * 4] = ((const float4*)z)[(rowBase + row) * 32 + q];
    }
    float zn[4];
#pragma unroll
    for (int i = 0; i < 4; ++i) zn[i] = zn2[rowBase + rgrp * 4 + i];
    __syncthreads();

    for (int cls = 0; cls < NCLS; ++cls) {
        int segLo = max(classStart[cls], splitLo);
        int segHi = min(classStart[cls + 1], splitHi);
        float accR[4] = {0.f, 0.f, 0.f, 0.f};

        for (int b0 = (segLo & ~127); b0 < segHi; b0 += 128) {
            __syncthreads();
            for (int t = tid; t < 128 * 32; t += 256) {
                int row = t >> 5, q = t & 31;
                *(float4*)&css[row * 132 + q * 4] =
                    ((const float4*)zc)[(b0 + row) * 32 + q];
            }
            __syncthreads();

            float acc[4][4];
#pragma unroll
            for (int i = 0; i < 4; ++i)
#pragma unroll
                for (int j = 0; j < 4; ++j) acc[i][j] = 0.f;

#pragma unroll 4
            for (int k = 0; k < 128; k += 4) {
                float4 a[4], c4[4];
#pragma unroll
                for (int i = 0; i < 4; ++i)
                    a[i] = *(const float4*)&zs[(rgrp * 4 + i) * 132 + k];
#pragma unroll
                for (int j = 0; j < 4; ++j)
                    c4[j] = *(const float4*)&css[(cgrp + 32 * j) * 132 + k];
#pragma unroll
                for (int i = 0; i < 4; ++i)
#pragma unroll
                    for (int j = 0; j < 4; ++j) {
                        acc[i][j] = fmaf(a[i].x, c4[j].x, acc[i][j]);
                        acc[i][j] = fmaf(a[i].y, c4[j].y, acc[i][j]);
                        acc[i][j] = fmaf(a[i].z, c4[j].z, acc[i][j]);
                        acc[i][j] = fmaf(a[i].w, c4[j].w, acc[i][j]);
                    }
            }

#pragma unroll
            for (int j = 0; j < 4; ++j) {
                int m = b0 + cgrp + 32 * j;
                float cm = cn[m];
                bool ok = (m >= segLo) && (m < segHi);
#pragma unroll
                for (int i = 0; i < 4; ++i) {
                    float sq = fmaxf(fmaf(-2.f, acc[i][j], zn[i] + cm), 1e-12f);
                    float d;
                    asm("sqrt.approx.f32 %0, %1;" : "=f"(d) : "f"(sq));
                    float e;
                    asm("ex2.approx.f32 %0, %1;" : "=f"(e)
                        : "f"(d * -1.4426950408889634f));
                    accR[i] += ok ? e : 0.f;
                }
            }
        }

#pragma unroll
        for (int i = 0; i < 4; ++i) {
            float s = accR[i];
#pragma unroll
            for (int off = 16; off > 0; off >>= 1) s += __shfl_xor_sync(FULLMASK, s, off);
            if (cgrp == 0)
                part[(sy * N + rowBase + rgrp * 4 + i) * NCLS + cls] = s;
        }
    }
}

// ---------------- finalize: combine splits, normalize, log ------------------
__global__ void finalize_k(const float* __restrict__ part, float* __restrict__ out, int N) {
    int n = blockIdx.x * blockDim.x + threadIdx.x;
    if (n >= N) return;
    float t[NCLS];
#pragma unroll
    for (int c = 0; c < NCLS; ++c) t[c] = 0.f;
    for (int s = 0; s < NSPLIT; ++s)
#pragma unroll
        for (int c = 0; c < NCLS; ++c) t[c] += part[(s * N + n) * NCLS + c];
    float tot = 0.f;
#pragma unroll
    for (int c = 0; c < NCLS; ++c) tot += t[c];
    float inv = 1.f / tot;
#pragma unroll
    for (int c = 0; c < NCLS; ++c) out[n * NCLS + c] = logf(fmaf(t[c], inv, 1e-7f));
}

// ---------------- launch ----------------------------------------------------
extern "C" void kernel_launch(void* const* d_in, const int* in_sizes, int n_in,
                              void* d_out, int out_size) {
    const float* x  = (const float*)d_in[0];
    const float* cx = (const float*)d_in[1];
    const int*   cy = (const int*)d_in[2];
    const float* W  = (const float*)d_in[3];
    const float* b  = (const float*)d_in[4];
    int N = in_sizes[0] / 128;
    int M = in_sizes[2];
    float* out = (float*)d_out;

    void *p_zc, *p_cn, *p_z, *p_zn2, *p_dest, *p_hist, *p_cs, *p_part;
    cudaGetSymbolAddress(&p_zc, g_zc);
    cudaGetSymbolAddress(&p_cn, g_cn);
    cudaGetSymbolAddress(&p_z, g_z);
    cudaGetSymbolAddress(&p_zn2, g_zn2);
    cudaGetSymbolAddress(&p_dest, g_destMap);
    cudaGetSymbolAddress(&p_hist, g_hist);
    cudaGetSymbolAddress(&p_cs, g_classStart);
    cudaGetSymbolAddress(&p_part, g_part);

    int NB = (M + 31) / 32;
    hist_k<<<NB, 32>>>(cy, M, (int*)p_hist);
    scan_k<<<1, 32>>>((int*)p_hist, NB, (int*)p_cs);
    scatter_k<<<NB, 32>>>(cy, M, (const int*)p_hist, (const int*)p_cs, (int*)p_dest);

    size_t smemEnc = (size_t)(128 * 132 + 32 * 132) * 4 + 32 * 4;
    cudaFuncSetAttribute(encode_k, cudaFuncAttributeMaxDynamicSharedMemorySize, (int)smemEnc);
    encode_k<<<(N + 31) / 32, 256, smemEnc>>>(x, N, nullptr, W, b,
                                              (float*)p_z, (float*)p_zn2);
    encode_k<<<(M + 31) / 32, 256, smemEnc>>>(cx, M, (const int*)p_dest, W, b,
                                              (float*)p_zc, (float*)p_cn);

    size_t smemMain = (size_t)(128 * 132 + 32 * 132) * 4;
    cudaFuncSetAttribute(nca_main_k, cudaFuncAttributeMaxDynamicSharedMemorySize, (int)smemMain);
    dim3 g(N / 32, NSPLIT);
    nca_main_k<<<g, 256, smemMain>>>((const float*)p_z, (const float*)p_zn2,
                                     (const float*)p_zc, (const float*)p_cn,
                                     (const int*)p_cs, (float*)p_part, M, N);

    finalize_k<<<(N + 255) / 256, 256>>>((const float*)p_part, out, N);
}

// round 4
// speedup vs baseline: 2.6849x; 2.6849x over previous
#include <cuda_runtime.h>
#include <cuda_bf16.h>
#include <math.h>
#include <stdint.h>

#define FULLMASK 0xffffffffu
#define NCLS 10
#define MAXM 131072
#define MAXN 2048
#define NSPLIT 9

// ---------------- scratch (static device globals; no allocation) ------------
__device__ __nv_bfloat16 g_zc_hi[MAXM * 128];
__device__ __nv_bfloat16 g_zc_lo[MAXM * 128];
__device__ float g_cn[MAXM];
__device__ __nv_bfloat16 g_z_hi[MAXN * 128];
__device__ __nv_bfloat16 g_z_lo[MAXN * 128];
__device__ float g_zn2[MAXN];
__device__ int   g_destMap[MAXM];
__device__ int   g_hist[(MAXM / 32) * NCLS];
__device__ int   g_classStart[NCLS + 1];
__device__ float g_part[NSPLIT * MAXN * NCLS];

// ---------------- PTX helpers (baseline sm_80+ only) -------------------------
__device__ __forceinline__ uint32_t smem_u32(const void* p) {
    uint32_t a;
    asm("{ .reg .u64 t; cvta.to.shared.u64 t, %1; cvt.u32.u64 %0, t; }" : "=r"(a) : "l"(p));
    return a;
}

#define CP16(saddr, gptr) \
    asm volatile("cp.async.cg.shared.global [%0], [%1], 16;" :: "r"(saddr), "l"(gptr))
#define CP_COMMIT() asm volatile("cp.async.commit_group;" ::: "memory")
#define CP_WAIT(n)  asm volatile("cp.async.wait_group %0;" :: "n"(n) : "memory")

#define LDSM4(r, addr) \
    asm volatile("ldmatrix.sync.aligned.m8n8.x4.shared.b16 {%0,%1,%2,%3}, [%4];" \
        : "=r"((r)[0]), "=r"((r)[1]), "=r"((r)[2]), "=r"((r)[3]) : "r"(addr))

#define MMA_BF16(d, a, b0v, b1v) \
    asm volatile("mma.sync.aligned.m16n8k16.row.col.f32.bf16.bf16.f32 " \
        "{%0,%1,%2,%3},{%4,%5,%6,%7},{%8,%9},{%0,%1,%2,%3};" \
        : "+f"((d)[0]), "+f"((d)[1]), "+f"((d)[2]), "+f"((d)[3]) \
        : "r"((a)[0]), "r"((a)[1]), "r"((a)[2]), "r"((a)[3]), "r"(b0v), "r"(b1v))

// ---------------- counting sort by class (deterministic, stable) ------------
__global__ void hist_k(const int* __restrict__ y, int M, int* __restrict__ hist) {
    int i = blockIdx.x * 32 + threadIdx.x;
    int c = (i < M) ? y[i] : -1;
#pragma unroll
    for (int cls = 0; cls < NCLS; ++cls) {
        unsigned b = __ballot_sync(FULLMASK, c == cls);
        if (threadIdx.x == 0) hist[blockIdx.x * NCLS + cls] = __popc(b);
    }
}

__global__ void scan_k(int* hist, int NB, int* classStart) {
    __shared__ int tot[NCLS];
    int c = threadIdx.x;
    if (c < NCLS) {
        int run = 0;
        for (int b = 0; b < NB; ++b) {
            int t = hist[b * NCLS + c];
            hist[b * NCLS + c] = run;
            run += t;
        }
        tot[c] = run;
    }
    __syncthreads();
    if (threadIdx.x == 0) {
        int a = 0;
        for (int i = 0; i < NCLS; ++i) { classStart[i] = a; a += tot[i]; }
        classStart[NCLS] = a;
    }
}

__global__ void scatter_k(const int* __restrict__ y, int M,
                          const int* __restrict__ hist,
                          const int* __restrict__ classStart,
                          int* __restrict__ dest) {
    int lane = threadIdx.x;
    int i = blockIdx.x * 32 + lane;
    int c = (i < M) ? y[i] : -1;
    unsigned mymask = 0;
#pragma unroll
    for (int cls = 0; cls < NCLS; ++cls) {
        unsigned b = __ballot_sync(FULLMASK, c == cls);
        if (c == cls) mymask = b;
    }
    if (i < M) {
        int rank = __popc(mymask & ((1u << lane) - 1u));
        dest[i] = classStart[c] + hist[blockIdx.x * NCLS + c] + rank;
    }
}

// ---------------- encoder: out[dest] = X[src]@W^T + b -> bf16 hi/lo + norms --
__global__ __launch_bounds__(256, 2)
void encode_k(const float* __restrict__ X, int n, const int* __restrict__ destMap,
              const float* __restrict__ W, const float* __restrict__ bias,
              __nv_bfloat16* __restrict__ outHi, __nv_bfloat16* __restrict__ outLo,
              float* __restrict__ outN) {
    extern __shared__ char smc[];
    float* sm = (float*)smc;
    float* ws = sm;                       // [128][132]
    float* xs = sm + 128 * 132;           // [32][132]
    int*   dests = (int*)(sm + 128 * 132 + 32 * 132);

    int tid = threadIdx.x;
    int base = blockIdx.x * 32;

    for (int t = tid; t < 128 * 32; t += 256) {
        int row = t >> 5, q = t & 31;
        float4 v = ((const float4*)W)[row * 32 + q];
        *(float4*)&ws[row * 132 + q * 4] = v;
    }
    for (int t = tid; t < 32 * 32; t += 256) {
        int row = t >> 5, q = t & 31;
        float4 v = make_float4(0.f, 0.f, 0.f, 0.f);
        if (base + row < n) v = ((const float4*)X)[(size_t)(base + row) * 32 + q];
        *(float4*)&xs[row * 132 + q * 4] = v;
    }
    if (tid < 32)
        dests[tid] = (base + tid < n) ? (destMap ? destMap[base + tid] : base + tid) : -1;
    __syncthreads();

    int cgrp = tid & 31, rgrp = tid >> 5;
    float acc[4][4];
#pragma unroll
    for (int i = 0; i < 4; ++i)
#pragma unroll
        for (int j = 0; j < 4; ++j) acc[i][j] = 0.f;

#pragma unroll 4
    for (int k = 0; k < 128; k += 4) {
        float4 a[4], w4[4];
#pragma unroll
        for (int i = 0; i < 4; ++i) a[i] = *(const float4*)&xs[(rgrp * 4 + i) * 132 + k];
#pragma unroll
        for (int j = 0; j < 4; ++j) w4[j] = *(const float4*)&ws[(cgrp + 32 * j) * 132 + k];
#pragma unroll
        for (int i = 0; i < 4; ++i)
#pragma unroll
            for (int j = 0; j < 4; ++j) {
                acc[i][j] = fmaf(a[i].x, w4[j].x, acc[i][j]);
                acc[i][j] = fmaf(a[i].y, w4[j].y, acc[i][j]);
                acc[i][j] = fmaf(a[i].z, w4[j].z, acc[i][j]);
                acc[i][j] = fmaf(a[i].w, w4[j].w, acc[i][j]);
            }
    }

    float nrm[4] = {0.f, 0.f, 0.f, 0.f};
#pragma unroll
    for (int j = 0; j < 4; ++j) {
        int dim = cgrp + 32 * j;
        float bb = bias[dim];
#pragma unroll
        for (int i = 0; i < 4; ++i) {
            float v = acc[i][j] + bb;
            acc[i][j] = v;
            nrm[i] = fmaf(v, v, nrm[i]);
        }
    }
#pragma unroll
    for (int i = 0; i < 4; ++i) {
        int d = dests[rgrp * 4 + i];
        if (d >= 0) {
#pragma unroll
            for (int j = 0; j < 4; ++j) {
                float v = acc[i][j];
                __nv_bfloat16 h = __float2bfloat16(v);
                __nv_bfloat16 l = __float2bfloat16(v - __bfloat162float(h));
                outHi[(size_t)d * 128 + cgrp + 32 * j] = h;
                outLo[(size_t)d * 128 + cgrp + 32 * j] = l;
            }
        }
        float s = nrm[i];
#pragma unroll
        for (int off = 16; off > 0; off >>= 1) s += __shfl_xor_sync(FULLMASK, s, off);
        if (cgrp == 0 && d >= 0) outN[d] = s;
    }
}

// ---------------- main: mma.sync bf16x3 dist + per-class numerators ---------
// smem layout (bytes). bf16 tiles are 128 rows x 256B with XOR-8 chunk swizzle.
#define SM_ZHI   0
#define SM_ZLO   32768
#define SM_B     65536     // 2 buffers x (hi 32768 + lo 32768)
#define SM_CN    196608    // 2 x 512
#define SM_SACC  197632    // 128*10 floats = 5120
#define SM_TOTAL 202752

// async-copy one 128x128 bf16 row-major tile into swizzled smem
__device__ __forceinline__ void issue_tile(uint32_t sbase, const uint4* __restrict__ g,
                                           int tid) {
#pragma unroll
    for (int t = 0; t < 8; ++t) {
        int idx = tid + t * 256;            // 0..2047, = row*16 + chunk
        int row = idx >> 4, c = idx & 15;
        uint32_t saddr = sbase + row * 256 + ((c ^ (row & 7)) << 4);
        CP16(saddr, g + idx);
    }
}

__global__ __launch_bounds__(256, 1)
void nca_mma_k(const __nv_bfloat16* __restrict__ zhi_g, const __nv_bfloat16* __restrict__ zlo_g,
               const float* __restrict__ zn2,
               const __nv_bfloat16* __restrict__ chi_g, const __nv_bfloat16* __restrict__ clo_g,
               const float* __restrict__ cn_g, const int* __restrict__ classStart,
               float* __restrict__ part, int M, int N) {
    extern __shared__ char smc[];
    char* sm = smc;
    const uint32_t sb = smem_u32(sm);
    const int tid = threadIdx.x;
    const int w = tid >> 5, lane = tid & 31;
    const int warpM = w & 1, warpN = w >> 1;   // 2 x 4 warp grid; 64 x 32 per warp
    const int q2 = (lane & 3) * 2;             // col pair base within n8
    const int tile = blockIdx.x, split = blockIdx.y;
    const int chunksTotal = M >> 7;
    const int cpb = (chunksTotal + NSPLIT - 1) / NSPLIT;
    const int cLo = split * cpb;
    const int cHi = min(cLo + cpb, chunksTotal);
    const int nch = cHi - cLo;

    // zero class accumulators
    for (int i = tid; i < 128 * NCLS; i += 256) ((float*)(sm + SM_SACC))[i] = 0.f;

    // class boundaries in regs
    int cs[NCLS + 1];
#pragma unroll
    for (int k = 0; k <= NCLS; ++k) cs[k] = classStart[k];

    // query norms for this thread's 8 rows
    float znr[4][2];
#pragma unroll
    for (int mi = 0; mi < 4; ++mi) {
        int r = tile * 128 + warpM * 64 + mi * 16 + (lane >> 2);
        znr[mi][0] = zn2[r];
        znr[mi][1] = zn2[r + 8];
    }

    // prologue: async-load z tiles + chunk 0
    issue_tile(sb + SM_ZHI, (const uint4*)zhi_g + (size_t)tile * 2048, tid);
    issue_tile(sb + SM_ZLO, (const uint4*)zlo_g + (size_t)tile * 2048, tid);
    issue_tile(sb + SM_B,         (const uint4*)chi_g + (size_t)cLo * 2048, tid);
    issue_tile(sb + SM_B + 32768, (const uint4*)clo_g + (size_t)cLo * 2048, tid);
    if (tid < 32) CP16(sb + SM_CN + tid * 16, (const float*)cn_g + (size_t)cLo * 128 + tid * 4);
    CP_COMMIT();

    // per-lane ldmatrix address precompute
    uint32_t aoff[4], asw[4];
#pragma unroll
    for (int mi = 0; mi < 4; ++mi) {
        int row = warpM * 64 + mi * 16 + (lane & 15);
        aoff[mi] = row * 256;
        asw[mi] = row & 7;
    }
    const int ach = lane >> 4;                 // A chunk offset
    uint32_t boff[2], bsw[2];
#pragma unroll
    for (int g = 0; g < 2; ++g) {
        int row = warpN * 32 + g * 16 + (lane & 7) + ((lane >> 4) << 3);
        boff[g] = row * 256;
        bsw[g] = row & 7;
    }
    const int bch = (lane >> 3) & 1;           // B chunk offset

    CP_WAIT(0);
    __syncthreads();

    for (int i = 0; i < nch; ++i) {
        const int cb = i & 1, nb = (i + 1) & 1;
        if (i + 1 < nch) {
            issue_tile(sb + SM_B + nb * 65536,
                       (const uint4*)chi_g + (size_t)(cLo + i + 1) * 2048, tid);
            issue_tile(sb + SM_B + nb * 65536 + 32768,
                       (const uint4*)clo_g + (size_t)(cLo + i + 1) * 2048, tid);
            if (tid < 32) CP16(sb + SM_CN + nb * 512 + tid * 16,
                               (const float*)cn_g + (size_t)(cLo + i + 1) * 128 + tid * 4);
            CP_COMMIT();
        }

        float acc[4][4][4];
#pragma unroll
        for (int mi = 0; mi < 4; ++mi)
#pragma unroll
            for (int ni = 0; ni < 4; ++ni)
#pragma unroll
                for (int k = 0; k < 4; ++k) acc[mi][ni][k] = 0.f;

        const uint32_t abaseH = sb + SM_ZHI;
        const uint32_t bbaseH = sb + SM_B + cb * 65536;

#pragma unroll
        for (int k8 = 0; k8 < 8; ++k8) {
            uint32_t ahi[4][4], alo[4][4], bhi[2][4], blo[2][4];
            int ca = 2 * k8 + ach;
            int cbk = 2 * k8 + bch;
#pragma unroll
            for (int mi = 0; mi < 4; ++mi) {
                uint32_t ad = abaseH + aoff[mi] + (((uint32_t)ca ^ asw[mi]) << 4);
                LDSM4(ahi[mi], ad);
                LDSM4(alo[mi], ad + 32768);
            }
#pragma unroll
            for (int g = 0; g < 2; ++g) {
                uint32_t bd = bbaseH + boff[g] + (((uint32_t)cbk ^ bsw[g]) << 4);
                LDSM4(bhi[g], bd);
                LDSM4(blo[g], bd + 32768);
            }
#pragma unroll
            for (int mi = 0; mi < 4; ++mi)
#pragma unroll
                for (int ni = 0; ni < 4; ++ni) {
                    int g = ni >> 1, p = (ni & 1) * 2;
                    MMA_BF16(acc[mi][ni], ahi[mi], bhi[g][p], bhi[g][p + 1]);
                    MMA_BF16(acc[mi][ni], ahi[mi], blo[g][p], blo[g][p + 1]);
                    MMA_BF16(acc[mi][ni], alo[mi], bhi[g][p], bhi[g][p + 1]);
                }
        }

        // candidate norms for this thread's 8 columns
        float cnv[4][2];
#pragma unroll
        for (int ni = 0; ni < 4; ++ni)
#pragma unroll
            for (int j = 0; j < 2; ++j)
                cnv[ni][j] = *(const float*)(sm + SM_CN + cb * 512 +
                                             (warpN * 32 + ni * 8 + q2 + j) * 4);

        // dist -> exp(-dist), in place
#pragma unroll
        for (int mi = 0; mi < 4; ++mi)
#pragma unroll
            for (int ni = 0; ni < 4; ++ni)
#pragma unroll
                for (int k = 0; k < 4; ++k) {
                    int h = k >> 1, j = k & 1;
                    float sq = fmaxf(fmaf(-2.f, acc[mi][ni][k], znr[mi][h] + cnv[ni][j]),
                                     1e-12f);
                    float dd;
                    asm("sqrt.approx.f32 %0, %1;" : "=f"(dd) : "f"(sq));
                    asm("ex2.approx.f32 %0, %1;" : "=f"(acc[mi][ni][k])
                        : "f"(dd * -1.4426950408889634f));
                }

        // class-segmented accumulation (candidates sorted by class)
        const int wb = (cLo + i) * 128 + warpN * 32;
        int c0 = 0;
        while (c0 < NCLS - 1 && cs[c0 + 1] <= wb) ++c0;
        int c1 = c0;
        while (c1 < NCLS - 1 && cs[c1 + 1] < wb + 32) ++c1;
        for (int c = c0; c <= c1; ++c) {
            int lo = max(cs[c] - wb, 0), hi = min(cs[c + 1] - wb, 32);
#pragma unroll
            for (int mi = 0; mi < 4; ++mi)
#pragma unroll
                for (int h = 0; h < 2; ++h) {
                    float s = 0.f;
#pragma unroll
                    for (int ni = 0; ni < 4; ++ni)
#pragma unroll
                        for (int j = 0; j < 2; ++j) {
                            int nl = ni * 8 + q2 + j;
                            s += (nl >= lo && nl < hi) ? acc[mi][ni][h * 2 + j] : 0.f;
                        }
                    s += __shfl_xor_sync(FULLMASK, s, 1);
                    s += __shfl_xor_sync(FULLMASK, s, 2);
                    if ((lane & 3) == 0) {
                        int r = warpM * 64 + mi * 16 + (lane >> 2) + h * 8;
                        atomicAdd((float*)(sm + SM_SACC) + r * NCLS + c, s);
                    }
                }
        }

        __syncthreads();              // all done with buffer cb before next overwrite
        if (i + 1 < nch) { CP_WAIT(0); }
        __syncthreads();
    }

    if (tid < 128) {
        int qg = tile * 128 + tid;
#pragma unroll
        for (int c = 0; c < NCLS; ++c)
            part[((size_t)split * N + qg) * NCLS + c] =
                ((float*)(sm + SM_SACC))[tid * NCLS + c];
    }
}

// ---------------- finalize: combine splits, normalize, log ------------------
__global__ void finalize_k(const float* __restrict__ part, float* __restrict__ out, int N) {
    int n = blockIdx.x * blockDim.x + threadIdx.x;
    if (n >= N) return;
    float t[NCLS];
#pragma unroll
    for (int c = 0; c < NCLS; ++c) t[c] = 0.f;
    for (int s = 0; s < NSPLIT; ++s)
#pragma unroll
        for (int c = 0; c < NCLS; ++c) t[c] += part[((size_t)s * N + n) * NCLS + c];
    float tot = 0.f;
#pragma unroll
    for (int c = 0; c < NCLS; ++c) tot += t[c];
    float inv = 1.f / tot;
#pragma unroll
    for (int c = 0; c < NCLS; ++c) out[n * NCLS + c] = logf(fmaf(t[c], inv, 1e-7f));
}

// ---------------- launch ----------------------------------------------------
extern "C" void kernel_launch(void* const* d_in, const int* in_sizes, int n_in,
                              void* d_out, int out_size) {
    const float* x  = (const float*)d_in[0];
    const float* cx = (const float*)d_in[1];
    const int*   cy = (const int*)d_in[2];
    const float* W  = (const float*)d_in[3];
    const float* b  = (const float*)d_in[4];
    int N = in_sizes[0] / 128;
    int M = in_sizes[2];
    float* out = (float*)d_out;

    void *p_zch, *p_zcl, *p_cn, *p_zh, *p_zl, *p_zn2, *p_dest, *p_hist, *p_cs, *p_part;
    cudaGetSymbolAddress(&p_zch, g_zc_hi);
    cudaGetSymbolAddress(&p_zcl, g_zc_lo);
    cudaGetSymbolAddress(&p_cn, g_cn);
    cudaGetSymbolAddress(&p_zh, g_z_hi);
    cudaGetSymbolAddress(&p_zl, g_z_lo);
    cudaGetSymbolAddress(&p_zn2, g_zn2);
    cudaGetSymbolAddress(&p_dest, g_destMap);
    cudaGetSymbolAddress(&p_hist, g_hist);
    cudaGetSymbolAddress(&p_cs, g_classStart);
    cudaGetSymbolAddress(&p_part, g_part);

    int NB = (M + 31) / 32;
    hist_k<<<NB, 32>>>(cy, M, (int*)p_hist);
    scan_k<<<1, 32>>>((int*)p_hist, NB, (int*)p_cs);
    scatter_k<<<NB, 32>>>(cy, M, (const int*)p_hist, (const int*)p_cs, (int*)p_dest);

    size_t smemEnc = (size_t)(128 * 132 + 32 * 132) * 4 + 32 * 4;
    cudaFuncSetAttribute(encode_k, cudaFuncAttributeMaxDynamicSharedMemorySize, (int)smemEnc);
    encode_k<<<(N + 31) / 32, 256, smemEnc>>>(x, N, nullptr, W, b,
        (__nv_bfloat16*)p_zh, (__nv_bfloat16*)p_zl, (float*)p_zn2);
    encode_k<<<(M + 31) / 32, 256, smemEnc>>>(cx, M, (const int*)p_dest, W, b,
        (__nv_bfloat16*)p_zch, (__nv_bfloat16*)p_zcl, (float*)p_cn);

    cudaFuncSetAttribute(nca_mma_k, cudaFuncAttributeMaxDynamicSharedMemorySize, SM_TOTAL);
    dim3 g(N / 128, NSPLIT);
    nca_mma_k<<<g, 256, SM_TOTAL>>>(
        (const __nv_bfloat16*)p_zh, (const __nv_bfloat16*)p_zl, (const float*)p_zn2,
        (const __nv_bfloat16*)p_zch, (const __nv_bfloat16*)p_zcl, (const float*)p_cn,
        (const int*)p_cs, (float*)p_part, M, N);

    finalize_k<<<(N + 255) / 256, 256>>>((const float*)p_part, out, N);
}